// round 15
// baseline (speedup 1.0000x reference)
#include <cuda_runtime.h>
#include <cuda_fp16.h>
#include <cstdint>

// EdgeBlock: out = relu(concat(cell[src],cell[dst],edge) @ W1 + b1) @ W2 + b2
// v10: persistent W-resident kernel. W1+W2 (128 KB fp16, swizzled) staged once
//      per CTA; grid = #SMs; fp16 gather via cp.async (cell pre-converted),
//      double-buffered A; edge chunk LDG-prefetched under gemm.
//      fp16 mma.m16n8k16, 32x64 warp tiles, 8 warps (4m x 2n), TILE_M=128.

#define THREADS  256
#define TILE_M   128
#define W_REGION 32768
#define A_REGION 32768
#define SM_A0    (4 * W_REGION)              // 131072
#define SM_A1    (SM_A0 + A_REGION)          // 163840
#define SMEM_BYTES (SM_A1 + A_REGION)        // 196608 -> 1 CTA/SM

// pre-transposed fp16 weights (n-major) + fp16 cell features
__device__ __half g_W1T[128 * 384];
__device__ __half g_W2T[128 * 128];
__device__ __half g_cell16[50000 * 128];

// swizzled byte offset in a [rows x 128 fp16] tile (256B rows, 16B chunks)
#define SWA(row, colh) \
    ((uint32_t)(row) * 256u + (((((uint32_t)(colh)) >> 3) ^ ((uint32_t)(row) & 7u)) << 4) \
     + (((uint32_t)(colh) & 7u) << 1))

// ---------------- helpers ----------------
__device__ __forceinline__ uint32_t smem_u32(const void* p) {
    uint32_t a;
    asm("{ .reg .u64 t; cvta.to.shared.u64 t, %1; cvt.u32.u64 %0, t; }" : "=r"(a) : "l"(p));
    return a;
}
__device__ __forceinline__ void ldm_x4(uint32_t* r, uint32_t addr) {
    asm volatile("ldmatrix.sync.aligned.m8n8.x4.shared.b16 {%0,%1,%2,%3}, [%4];"
                 : "=r"(r[0]), "=r"(r[1]), "=r"(r[2]), "=r"(r[3]) : "r"(addr));
}
__device__ __forceinline__ void mma_f16(float* d, const uint32_t* a, const uint32_t* b) {
    asm volatile(
        "mma.sync.aligned.m16n8k16.row.col.f32.f16.f16.f32 "
        "{%0,%1,%2,%3}, {%4,%5,%6,%7}, {%8,%9}, {%0,%1,%2,%3};"
        : "+f"(d[0]), "+f"(d[1]), "+f"(d[2]), "+f"(d[3])
        : "r"(a[0]), "r"(a[1]), "r"(a[2]), "r"(a[3]), "r"(b[0]), "r"(b[1]));
}
__device__ __forceinline__ void cp16(uint32_t dst, const void* src) {
    asm volatile("cp.async.cg.shared.global [%0], [%1], 16;" :: "r"(dst), "l"(src));
}
#define CP_COMMIT() asm volatile("cp.async.commit_group;" ::: "memory")
#define CP_WAIT(n)  asm volatile("cp.async.wait_group %0;" :: "n"(n) : "memory")

// one warp's 32x64 share of a 128(M) x 128(N) x 128(K) fp16 chunk, 8 k16-steps
__device__ __forceinline__ void gemm_chunk(uint32_t At, uint32_t Wt,
                                           float acc[2][8][4],
                                           int wm, int wn, int lane)
{
    const int sub = lane >> 3, l7 = lane & 7;
    const int arow = wm * 32 + (sub & 1) * 8 + l7;
    const int akol = (sub >> 1) * 8;
    const int brow = wn * 64 + (sub >> 1) * 8 + l7;
    const int bkol = (sub & 1) * 8;
#pragma unroll 2
    for (int kk = 0; kk < 8; ++kk) {
        uint32_t a[2][4];
#pragma unroll
        for (int t = 0; t < 2; ++t)
            ldm_x4(a[t], At + SWA(arow + t * 16, kk * 16 + akol));
        uint32_t b[4][4];
#pragma unroll
        for (int p = 0; p < 4; ++p)
            ldm_x4(b[p], Wt + SWA(brow + p * 16, kk * 16 + bkol));
#pragma unroll
        for (int t = 0; t < 2; ++t)
#pragma unroll
            for (int p = 0; p < 4; ++p) {
                mma_f16(acc[t][2 * p],     a[t], &b[p][0]);
                mma_f16(acc[t][2 * p + 1], a[t], &b[p][2]);
            }
    }
}

// gather one 128-row fp16 A chunk via cp.async from pre-converted cell
__device__ __forceinline__ void gather_cp(uint32_t dstA, const int* __restrict__ eidx,
                                          int base_off, int e0, int E, int tid)
{
    int row = tid >> 1;
    int e = e0 + row; int eL = (e < E) ? e : (E - 1);
    int idx = __ldg(eidx + base_off + eL);
    const __half* src = g_cell16 + (size_t)idx * 128;
    int h8 = (tid & 1) * 8;
#pragma unroll
    for (int i = 0; i < 8; ++i)
        cp16(dstA + SWA(row, (h8 + i) * 8), src + (size_t)(h8 + i) * 8);
}

// ---------------- prep: W transpose->fp16, cell->fp16 ----------------
__global__ void prep_kernel(const float* __restrict__ cell,
                            const float* __restrict__ W1,
                            const float* __restrict__ W2) {
    int i = blockIdx.x * blockDim.x + threadIdx.x;
    if (i < 50000 * 128)
        g_cell16[i] = __float2half_rn(cell[i]);
    if (i < 384 * 128) {
        int k = i >> 7, n = i & 127;
        g_W1T[n * 384 + k] = __float2half_rn(W1[i]);
    }
    if (i < 128 * 128) {
        int k = i >> 7, n = i & 127;
        g_W2T[n * 128 + k] = __float2half_rn(W2[i]);
    }
}

// ---------------- main persistent kernel ----------------
__global__ void __launch_bounds__(THREADS, 1)
edgeblock_pers(const float* __restrict__ edge,
               const float* __restrict__ b1,
               const float* __restrict__ b2,
               const int*   __restrict__ eidx,
               float* __restrict__ out,
               int E)
{
    extern __shared__ __align__(16) char sm[];
    const uint32_t sb   = smem_u32(sm);
    const uint32_t W_u  = sb;
    const uint32_t A0_u = sb + SM_A0;
    const uint32_t A1_u = sb + SM_A1;

    const int tid = threadIdx.x, wid = tid >> 5, lane = tid & 31;
    const int wm = wid >> 1, wn = wid & 1;      // 4m x 2n grid, 32x64 warp tiles

    // ---- preload all W tiles (once) ----
#pragma unroll
    for (int r = 0; r < 3; ++r)
#pragma unroll
        for (int i = 0; i < 8; ++i) {
            int idx = i * 256 + tid;
            int row = idx >> 4, c8 = idx & 15;
            cp16(W_u + r * W_REGION + SWA(row, c8 * 8),
                 g_W1T + (size_t)row * 384 + r * 128 + c8 * 8);
        }
#pragma unroll
    for (int i = 0; i < 8; ++i) {
        int idx = i * 256 + tid;
        int row = idx >> 4, c8 = idx & 15;
        cp16(W_u + 3 * W_REGION + SWA(row, c8 * 8),
             g_W2T + (size_t)row * 128 + c8 * 8);
    }
    CP_COMMIT();                                 // group: W

    const int ntiles = (E + TILE_M - 1) / TILE_M;
    int tile = blockIdx.x;
    if (tile >= ntiles) return;

    // hoist biases (loop-invariant per thread)
    const int colb = wn * 64 + (lane & 3) * 2;
    const int rowb = wm * 32 + (lane >> 2);
    float b1x[8], b1y[8], b2x[8], b2y[8];
#pragma unroll
    for (int j = 0; j < 8; ++j) {
        b1x[j] = __ldg(&b1[colb + j * 8]); b1y[j] = __ldg(&b1[colb + j * 8 + 1]);
        b2x[j] = __ldg(&b2[colb + j * 8]); b2y[j] = __ldg(&b2[colb + j * 8 + 1]);
    }

    gather_cp(A0_u, eidx, 0, tile * TILE_M, E, tid);   // src chunk, first tile
    CP_COMMIT();                                 // group: g0

#pragma unroll 1
    for (; tile < ntiles; tile += gridDim.x) {
        const int e0 = tile * TILE_M;

        gather_cp(A1_u, eidx, E, e0, E, tid);    // dst chunk
        CP_COMMIT();                             // group: g1

        float acc[2][8][4];
#pragma unroll
        for (int t = 0; t < 2; ++t)
#pragma unroll
            for (int j = 0; j < 8; ++j)
#pragma unroll
                for (int c = 0; c < 4; ++c) acc[t][j][c] = 0.0f;

        CP_WAIT(1);                              // g0 (and W on first iter) done
        __syncthreads();
        gemm_chunk(A0_u, W_u, acc, wm, wn, lane);

        // edge-chunk prefetch: contiguous rows, MLP 16, hides under gemm(ch1)
        float4 ev[16];
        {
            int row = tid >> 1;
            int e = e0 + row; int eL = (e < E) ? e : (E - 1);
            const float4* bp = reinterpret_cast<const float4*>(edge + (size_t)eL * 128);
            int c0 = (tid & 1) * 16;
#pragma unroll
            for (int i = 0; i < 16; ++i) ev[i] = bp[c0 + i];
        }

        CP_WAIT(0);                              // g1 done
        __syncthreads();
        gemm_chunk(A1_u, W_u + W_REGION, acc, wm, wn, lane);

        // edge cvt + STS -> A0 (free after gemm ch0)
        {
            int row = tid >> 1;
            int c0 = (tid & 1) * 16;
#pragma unroll
            for (int i = 0; i < 16; ++i) {
                __half2 h0 = __float22half2_rn(make_float2(ev[i].x, ev[i].y));
                __half2 h1 = __float22half2_rn(make_float2(ev[i].z, ev[i].w));
                uint64_t q = ((uint64_t)*reinterpret_cast<uint32_t*>(&h1) << 32) |
                              *reinterpret_cast<uint32_t*>(&h0);
                *reinterpret_cast<uint64_t*>(sm + SM_A0 + SWA(row, (c0 + i) * 4)) = q;
            }
        }
        __syncthreads();
        gemm_chunk(A0_u, W_u + 2 * W_REGION, acc, wm, wn, lane);

        // epilogue1: h = relu(acc+b1) -> fp16 -> A1 (free after gemm ch1)
#pragma unroll
        for (int t = 0; t < 2; ++t)
#pragma unroll
            for (int j = 0; j < 8; ++j) {
#pragma unroll
                for (int half = 0; half < 2; ++half) {
                    int row = rowb + t * 16 + half * 8;
                    __half2 h2 = __float22half2_rn(make_float2(
                        fmaxf(acc[t][j][2 * half]     + b1x[j], 0.0f),
                        fmaxf(acc[t][j][2 * half + 1] + b1y[j], 0.0f)));
                    *reinterpret_cast<uint32_t*>(sm + SM_A1 + SWA(row, colb + j * 8)) =
                        *reinterpret_cast<uint32_t*>(&h2);
                }
#pragma unroll
                for (int c = 0; c < 4; ++c) acc[0][j][c] = acc[0][j][c]; // keep shape
            }
#pragma unroll
        for (int t = 0; t < 2; ++t)
#pragma unroll
            for (int j = 0; j < 8; ++j)
#pragma unroll
                for (int c = 0; c < 4; ++c) acc[t][j][c] = 0.0f;
        __syncthreads();

        // overlap next tile's src gather with gemm2
        int tnext = tile + gridDim.x;
        if (tnext < ntiles) {
            gather_cp(A0_u, eidx, 0, tnext * TILE_M, E, tid);
            CP_COMMIT();                         // group: g0 (next iter)
        }

        gemm_chunk(A1_u, W_u + 3 * W_REGION, acc, wm, wn, lane);
        __syncthreads();                         // protect A1 before next g1

        // epilogue2: + b2, store
#pragma unroll
        for (int t = 0; t < 2; ++t)
#pragma unroll
            for (int j = 0; j < 8; ++j) {
#pragma unroll
                for (int half = 0; half < 2; ++half) {
                    int row = rowb + t * 16 + half * 8;
                    int e = e0 + row;
                    if (e < E) {
                        float2 o = make_float2(acc[t][j][2 * half] + b2x[j],
                                               acc[t][j][2 * half + 1] + b2y[j]);
                        *reinterpret_cast<float2*>(out + (size_t)e * 128 + colb + j * 8) = o;
                    }
                }
            }
    }
}

extern "C" void kernel_launch(void* const* d_in, const int* in_sizes, int n_in,
                              void* d_out, int out_size) {
    const float* cell = (const float*)d_in[0];   // [50000,128]
    const float* edge = (const float*)d_in[1];   // [E,128]
    const float* W1   = (const float*)d_in[2];   // [384,128]
    const float* b1   = (const float*)d_in[3];   // [128]
    const float* W2   = (const float*)d_in[4];   // [128,128]
    const float* b2   = (const float*)d_in[5];   // [128]
    const int*   eidx = (const int*)d_in[6];     // [2,E]
    float* out = (float*)d_out;

    int E = in_sizes[6] / 2;

    prep_kernel<<<(50000 * 128 + 255) / 256, 256>>>(cell, W1, W2);

    int nsm = 148;
    cudaDeviceGetAttribute(&nsm, cudaDevAttrMultiProcessorCount, 0);

    cudaFuncSetAttribute(edgeblock_pers,
                         cudaFuncAttributeMaxDynamicSharedMemorySize, SMEM_BYTES);
    edgeblock_pers<<<nsm, THREADS, SMEM_BYTES>>>(edge, b1, b2, eidx, out, E);
}

// round 16
// speedup vs baseline: 1.2983x; 1.2983x over previous
#include <cuda_runtime.h>
#include <cuda_fp16.h>
#include <cstdint>

// EdgeBlock: out = relu(concat(cell[src],cell[dst],edge) @ W1 + b1) @ W2 + b2
// v11 = v8 (fp16 m16n8k16, 32x64 warp tiles, 48 KB swizzled smem, TILE_M=64,
//       128 thr, 4 CTAs/SM) + cell gather via cp.async from pre-converted
//       fp16 cell (g_cell16): removes LDG+cvt+STS for 2 of 3 K-chunks.

#define THREADS 128
#define TILE_M  64
#define A_BYTES 16384                   // 64 x 128 fp16, swizzled (256B rows)
#define W_BYTES 32768                   // 128 x 128 fp16, swizzled
#define SMEM_BYTES (A_BYTES + W_BYTES)  // 49152 -> 4 CTAs/SM (regs<=128)

// pre-transposed fp16 weights (n-major) + fp16 cell features
__device__ __half g_W1T[128 * 384];
__device__ __half g_W2T[128 * 128];
__device__ __half g_cell16[50000 * 128];

// swizzled byte offset in a [rows x 128 fp16] tile (256B rows, 16B chunks)
#define SWA(row, colh) \
    ((uint32_t)(row) * 256u + (((((uint32_t)(colh)) >> 3) ^ ((uint32_t)(row) & 7u)) << 4) \
     + (((uint32_t)(colh) & 7u) << 1))

// ---------------- helpers ----------------
__device__ __forceinline__ uint32_t smem_u32(const void* p) {
    uint32_t a;
    asm("{ .reg .u64 t; cvta.to.shared.u64 t, %1; cvt.u32.u64 %0, t; }" : "=r"(a) : "l"(p));
    return a;
}
__device__ __forceinline__ void ldm_x4(uint32_t* r, uint32_t addr) {
    asm volatile("ldmatrix.sync.aligned.m8n8.x4.shared.b16 {%0,%1,%2,%3}, [%4];"
                 : "=r"(r[0]), "=r"(r[1]), "=r"(r[2]), "=r"(r[3]) : "r"(addr));
}
__device__ __forceinline__ void mma_f16(float* d, const uint32_t* a, const uint32_t* b) {
    asm volatile(
        "mma.sync.aligned.m16n8k16.row.col.f32.f16.f16.f32 "
        "{%0,%1,%2,%3}, {%4,%5,%6,%7}, {%8,%9}, {%0,%1,%2,%3};"
        : "+f"(d[0]), "+f"(d[1]), "+f"(d[2]), "+f"(d[3])
        : "r"(a[0]), "r"(a[1]), "r"(a[2]), "r"(a[3]), "r"(b[0]), "r"(b[1]));
}
__device__ __forceinline__ void cp16(uint32_t dst, const void* src) {
    asm volatile("cp.async.cg.shared.global [%0], [%1], 16;" :: "r"(dst), "l"(src));
}
#define CP_COMMIT() asm volatile("cp.async.commit_group;" ::: "memory")
#define CP_WAIT0()  asm volatile("cp.async.wait_group 0;" ::: "memory")

// one warp's 32x64 share of a 64(M) x 128(N) x 128(K) fp16 chunk, 8 k16-steps
__device__ __forceinline__ void gemm_chunk(uint32_t At, uint32_t Wt,
                                           float acc[2][8][4],
                                           int wm, int wn, int lane)
{
    const int sub = lane >> 3, l7 = lane & 7;
    const int arow = wm * 32 + (sub & 1) * 8 + l7;     // + t*16
    const int akol = (sub >> 1) * 8;                   // + kk*16
    const int brow = wn * 64 + (sub >> 1) * 8 + l7;    // + p*16
    const int bkol = (sub & 1) * 8;                    // + kk*16
#pragma unroll 2
    for (int kk = 0; kk < 8; ++kk) {
        uint32_t a[2][4];
#pragma unroll
        for (int t = 0; t < 2; ++t)
            ldm_x4(a[t], At + SWA(arow + t * 16, kk * 16 + akol));
        uint32_t b[4][4];
#pragma unroll
        for (int p = 0; p < 4; ++p)
            ldm_x4(b[p], Wt + SWA(brow + p * 16, kk * 16 + bkol));
#pragma unroll
        for (int t = 0; t < 2; ++t)
#pragma unroll
            for (int p = 0; p < 4; ++p) {
                mma_f16(acc[t][2 * p],     a[t], &b[p][0]);
                mma_f16(acc[t][2 * p + 1], a[t], &b[p][2]);
            }
    }
}

// stage one 128n x 128k fp16 tile via cp.async into swizzled layout
__device__ __forceinline__ void stage_w(uint32_t Wt, const __half* src,
                                        int src_stride, int tid)
{
#pragma unroll
    for (int i = 0; i < 16; ++i) {
        int idx = i * 128 + tid;          // 2048 16B-groups
        int row = idx >> 4, c8 = idx & 15;
        cp16(Wt + SWA(row, c8 * 8), src + row * src_stride + c8 * 8);
    }
}

// gather one 64-row fp16 A chunk via cp.async from pre-converted cell
__device__ __forceinline__ void gather_cp(uint32_t dstA, const int* __restrict__ eidx,
                                          int base_off, int e0, int E, int tid)
{
    int row = tid >> 1;                   // 0..63
    int e = e0 + row; int eL = (e < E) ? e : (E - 1);
    int idx = __ldg(eidx + base_off + eL);
    const __half* src = g_cell16 + (size_t)idx * 128;
    int h8 = (tid & 1) * 8;               // 16B-chunk base (0 or 8)
#pragma unroll
    for (int i = 0; i < 8; ++i)
        cp16(dstA + SWA(row, (h8 + i) * 8), src + (size_t)(h8 + i) * 8);
}

// ---------------- prep: W transpose->fp16, cell->fp16 ----------------
__global__ void prep_kernel(const float* __restrict__ cell,
                            const float* __restrict__ W1,
                            const float* __restrict__ W2) {
    int i = blockIdx.x * blockDim.x + threadIdx.x;
    if (i < 50000 * 128)
        g_cell16[i] = __float2half_rn(cell[i]);
    if (i < 384 * 128) {
        int k = i >> 7, n = i & 127;
        g_W1T[n * 384 + k] = __float2half_rn(W1[i]);
    }
    if (i < 128 * 128) {
        int k = i >> 7, n = i & 127;
        g_W2T[n * 128 + k] = __float2half_rn(W2[i]);
    }
}

// ---------------- main fused kernel ----------------
__global__ void __launch_bounds__(THREADS, 4)
edgeblock_mma(const float* __restrict__ edge,
              const float* __restrict__ b1,
              const float* __restrict__ b2,
              const int*   __restrict__ eidx,
              float* __restrict__ out,
              int E)
{
    extern __shared__ __align__(16) char sm[];
    char* At = sm;
    const uint32_t sb   = smem_u32(sm);
    const uint32_t At_u = sb;
    const uint32_t Wt_u = sb + A_BYTES;

    const int tid = threadIdx.x, wid = tid >> 5, lane = tid & 31;
    const int wm = wid & 1, wn = wid >> 1;      // 2m x 2n grid, 32x64 warp tiles
    const int e0 = blockIdx.x * TILE_M;

    const int g_rsub = wid * 4 + (lane >> 3);   // row within 16-row group (edge ch)
    const int g_l7   = lane & 7;

    float acc[2][8][4];
#pragma unroll
    for (int t = 0; t < 2; ++t)
#pragma unroll
        for (int j = 0; j < 8; ++j)
#pragma unroll
            for (int c = 0; c < 4; ++c) acc[t][j][c] = 0.0f;

    // ===== GEMM1: 3 K-chunks of 128 =====
#pragma unroll 1
    for (int ch = 0; ch < 3; ++ch) {
        stage_w(Wt_u, g_W1T + ch * 128, 384, tid);   // async W chunk

        if (ch < 2) {
            // cell gather: pure cp.async from fp16 cell (no regs, no cvt)
            gather_cp(At_u, eidx, ch == 0 ? 0 : E, e0, E, tid);
            CP_COMMIT();
        } else {
            CP_COMMIT();
            // edge chunk: LDG f32 + cvt + STS (4 batches of 16 rows, MLP 4)
#pragma unroll 1
            for (int b = 0; b < 4; ++b) {
                int row = b * 16 + g_rsub;
                int e = e0 + row; int eL = (e < E) ? e : (E - 1);
                const float* base = edge + (size_t)eL * 128;
                float4 v[4];
#pragma unroll
                for (int i = 0; i < 4; ++i)
                    v[i] = reinterpret_cast<const float4*>(base)[g_l7 + 8 * i];
#pragma unroll
                for (int i = 0; i < 4; ++i) {
                    int c4 = g_l7 + 8 * i;
                    __half2 h0 = __float22half2_rn(make_float2(v[i].x, v[i].y));
                    __half2 h1 = __float22half2_rn(make_float2(v[i].z, v[i].w));
                    uint64_t q = ((uint64_t)*reinterpret_cast<uint32_t*>(&h1) << 32) |
                                  *reinterpret_cast<uint32_t*>(&h0);
                    *reinterpret_cast<uint64_t*>(At + SWA(row, c4 * 4)) = q;
                }
            }
        }

        CP_WAIT0();
        __syncthreads();
        gemm_chunk(At_u, Wt_u, acc, wm, wn, lane);
        __syncthreads();
    }

    // ===== epilogue1: h = relu(acc+b1) -> fp16 -> A tile; prefetch W2 =====
    stage_w(Wt_u, g_W2T, 128, tid);
    CP_COMMIT();
    {
        const int colb = wn * 64 + (lane & 3) * 2;
        const int rowb = wm * 32 + (lane >> 2);
#pragma unroll
        for (int t = 0; t < 2; ++t)
#pragma unroll
            for (int j = 0; j < 8; ++j) {
                int col = colb + j * 8;
                float bx = __ldg(&b1[col]), by = __ldg(&b1[col + 1]);
#pragma unroll
                for (int half = 0; half < 2; ++half) {
                    int row = rowb + t * 16 + half * 8;
                    __half2 h2 = __float22half2_rn(make_float2(
                        fmaxf(acc[t][j][2 * half]     + bx, 0.0f),
                        fmaxf(acc[t][j][2 * half + 1] + by, 0.0f)));
                    *reinterpret_cast<uint32_t*>(At + SWA(row, col)) =
                        *reinterpret_cast<uint32_t*>(&h2);
                }
            }
#pragma unroll
        for (int t = 0; t < 2; ++t)
#pragma unroll
            for (int j = 0; j < 8; ++j)
#pragma unroll
                for (int c = 0; c < 4; ++c) acc[t][j][c] = 0.0f;
    }
    CP_WAIT0();
    __syncthreads();

    // ===== GEMM2: [64 x 128] @ W2 =====
    gemm_chunk(At_u, Wt_u, acc, wm, wn, lane);

    // ===== epilogue2: + b2, store =====
    {
        const int colb = wn * 64 + (lane & 3) * 2;
        const int rowb = wm * 32 + (lane >> 2);
#pragma unroll
        for (int t = 0; t < 2; ++t)
#pragma unroll
            for (int j = 0; j < 8; ++j) {
                int col = colb + j * 8;
                float bx = __ldg(&b2[col]), by = __ldg(&b2[col + 1]);
#pragma unroll
                for (int half = 0; half < 2; ++half) {
                    int row = rowb + t * 16 + half * 8;
                    int e = e0 + row;
                    if (e < E) {
                        float2 o = make_float2(acc[t][j][2 * half] + bx,
                                               acc[t][j][2 * half + 1] + by);
                        *reinterpret_cast<float2*>(out + (size_t)e * 128 + col) = o;
                    }
                }
            }
    }
}

extern "C" void kernel_launch(void* const* d_in, const int* in_sizes, int n_in,
                              void* d_out, int out_size) {
    const float* cell = (const float*)d_in[0];   // [50000,128]
    const float* edge = (const float*)d_in[1];   // [E,128]
    const float* W1   = (const float*)d_in[2];   // [384,128]
    const float* b1   = (const float*)d_in[3];   // [128]
    const float* W2   = (const float*)d_in[4];   // [128,128]
    const float* b2   = (const float*)d_in[5];   // [128]
    const int*   eidx = (const int*)d_in[6];     // [2,E]
    float* out = (float*)d_out;

    int E = in_sizes[6] / 2;

    prep_kernel<<<(50000 * 128 + 255) / 256, 256>>>(cell, W1, W2);

    cudaFuncSetAttribute(edgeblock_mma,
                         cudaFuncAttributeMaxDynamicSharedMemorySize, SMEM_BYTES);
    int grid = (E + TILE_M - 1) / TILE_M;
    edgeblock_mma<<<grid, THREADS, SMEM_BYTES>>>(edge, b1, b2, eidx, out, E);
}